// round 16
// baseline (speedup 1.0000x reference)
#include <cuda_runtime.h>
#include <math.h>
#include <stdint.h>

#define NA    9216       // 96*96
#define CDIM  1280
#define NPIX  4096       // 64*64
#define HW48  2304       // 48*48
#define DCHK  16         // d-chunks for column dots
#define DSZ   (CDIM / DCHK)   // 80

// ---------------- scratch (device globals; no allocation allowed) ----------
__device__ float g_t[CDIM];               // t_d
__device__ float g_w[CDIM];               // w_d
__device__ float g_up[NPIX * DCHK];       // u partials, [pixel][chunk]
__device__ float g_yp[NPIX * DCHK];       // y partials, [pixel][chunk]
__device__ float g_v[NPIX];               // adjoint-resized invZ
__device__ float g_invZ[NA];
__device__ float g_s0p[36];               // per-block invZ sums
__device__ unsigned char g_flag[NA];
__device__ float g_x1[HW48];
__device__ float g_out48[HW48];
__device__ int4   g_it4[96];              // cubic taps 64->96
__device__ float4 g_wt4[96];
__device__ float  g_W[96 * 64];           // dense resize matrix W[o][i]
__device__ float  g_sink;                 // prefetch DCE guard

// ---------------- cubic kernel ----------------------------------------------
__device__ __forceinline__ float keys_cubic(float x) {
    x = fabsf(x);
    if (x < 1.f)  return ((1.5f * x - 2.5f) * x) * x + 1.f;
    if (x < 2.f)  return ((-0.5f * x + 2.5f) * x - 4.f) * x + 2.f;
    return 0.f;
}

__device__ __forceinline__ int tap_lo(int yo0) {
    float s = (yo0 + 0.5f) * (64.f / 96.f) - 0.5f;
    return max(0, (int)floorf(s) - 1);
}

// sum the DCHK=16 consecutive partials of pixel p (4 x float4)
__device__ __forceinline__ float sum16(const float* part, int p) {
    const float4* q = (const float4*)(part + p * DCHK);
    float4 a = q[0], b = q[1], c = q[2], d = q[3];
    return ((a.x+a.y)+(a.z+a.w)) + ((b.x+b.y)+(b.z+b.w))
         + ((c.x+c.y)+(c.z+c.w)) + ((d.x+d.y)+(d.z+d.w));
}

// ---------------- L2 warm: touch every 32B sector of a buffer ---------------
__global__ void k_pref(const float* __restrict__ A, int nsec) {
    int i = blockIdx.x * 256 + threadIdx.x;
    float acc = 0.f;
    for (int s = i; s < nsec; s += 256 * 256)
        acc += A[(size_t)s * 8];
    if (acc == 1.2345e37f) g_sink = acc;
}

// ---------------- init: flag (blocks 0..35) + weights (block 36) ------------
__global__ void k_init(const float* __restrict__ guid) {
    if (blockIdx.x < 36) {
        int i = blockIdx.x * 256 + threadIdx.x;
        int by = i / 96, bx = i % 96;
        const float* p = guid + (by * 8) * 768 + bx * 8;
        bool all = true;
        #pragma unroll
        for (int dy = 0; dy < 8; dy++)
            #pragma unroll
            for (int dx = 0; dx < 8; dx++)
                all = all && (p[dy * 768 + dx] > 0.5f);
        g_flag[i] = all ? 1 : 0;
        return;
    }
    int o = threadIdx.x;
    if (o < 96) {
        float s = (o + 0.5f) * (64.f / 96.f) - 0.5f;
        int fl = (int)floorf(s);
        int idx[4]; float w[4]; float tot = 0.f;
        #pragma unroll
        for (int t = 0; t < 4; t++) {
            int ii = fl - 1 + t;
            float ww = (ii >= 0 && ii < 64) ? keys_cubic(s - (float)ii) : 0.f;
            idx[t] = min(max(ii, 0), 63);
            w[t] = ww;
            tot += ww;
        }
        float inv = 1.f / tot;
        g_it4[o] = make_int4(idx[0], idx[1], idx[2], idx[3]);
        g_wt4[o] = make_float4(w[0]*inv, w[1]*inv, w[2]*inv, w[3]*inv);
        float row[64];
        #pragma unroll
        for (int i = 0; i < 64; i++) row[i] = 0.f;
        #pragma unroll
        for (int t = 0; t < 4; t++) row[idx[t]] += w[t] * inv;
        for (int i = 0; i < 64; i++) g_W[o * 64 + i] = row[i];
    }
}

// ---------------- t_d = <ft_cor[d], Wmap>, self-contained weights -----------
__global__ __launch_bounds__(256) void k_t(const float* __restrict__ ft) {
    __shared__ float red[256];
    __shared__ float scw[64];
    __shared__ int   sIdx[384];
    __shared__ float sWt[384];
    int t = threadIdx.x;
    if (t < 96) {
        float s = (t + 0.5f) * (64.f / 96.f) - 0.5f;
        int fl = (int)floorf(s);
        float tot = 0.f; float w[4]; int id[4];
        #pragma unroll
        for (int k = 0; k < 4; k++) {
            int ii = fl - 1 + k;
            float ww = (ii >= 0 && ii < 64) ? keys_cubic(s - (float)ii) : 0.f;
            id[k] = min(max(ii, 0), 63);
            w[k] = ww;
            tot += ww;
        }
        float inv = 1.f / tot;
        #pragma unroll
        for (int k = 0; k < 4; k++) { sIdx[t*4+k] = id[k]; sWt[t*4+k] = w[k]*inv; }
    }
    __syncthreads();
    if (t < 64) {
        float a = 0.f;
        #pragma unroll 8
        for (int e = 0; e < 384; e++)
            a += (sIdx[e] == t) ? sWt[e] : 0.f;
        scw[t] = a;
    }
    __syncthreads();
    int d = blockIdx.x;
    const float4* row = (const float4*)(ft + (size_t)d * NPIX);
    float acc = 0.f;
    #pragma unroll
    for (int q = t; q < 1024; q += 256) {
        float4 v = row[q];
        float4 cx = ((const float4*)scw)[q & 15];
        float cy = scw[q >> 4];
        acc += cy * (cx.x*v.x + cx.y*v.y + cx.z*v.z + cx.w*v.w);
    }
    red[t] = acc;
    __syncthreads();
    for (int s = 128; s; s >>= 1) {
        if (t < s) red[t] += red[t + s];
        __syncthreads();
    }
    if (t == 0) g_t[d] = red[0];
}

// ---------------- u partials: 512 blocks (128 thr), [pixel][chunk] ----------
__global__ __launch_bounds__(128) void k_upart(const float* __restrict__ ref) {
    __shared__ float st[DSZ];
    int t = threadIdx.x;
    int p  = blockIdx.x * 128 + t;            // 32 x-blocks
    int c0 = blockIdx.y * DSZ;
    if (t < DSZ) st[t] = g_t[c0 + t];
    __syncthreads();
    float acc = 0.f;
    #pragma unroll
    for (int dd = 0; dd < DSZ; dd++)
        acc += ref[(size_t)(c0 + dd) * NPIX + p] * st[dd];
    g_up[p * DCHK + blockIdx.y] = acc;
}

// ---------------- fused: u-window + invZ + s0 partial ------------------------
__global__ void k_invz() {
    __shared__ float su[8][64];
    __shared__ float red[256];
    int b = blockIdx.x, t = threadIdx.x;
    int j0 = b * 256;
    int ty_lo = tap_lo(j0 / 96);
    int nr = min(8, 64 - ty_lo);
    for (int idx = t; idx < nr * 64; idx += 256) {
        int p = (ty_lo + (idx >> 6)) * 64 + (idx & 63);
        su[idx >> 6][idx & 63] = sum16(g_up, p);
    }
    __syncthreads();
    int j = j0 + t;
    int yo = j / 96, xo = j % 96;
    int4 iy = g_it4[yo]; float4 wy = g_wt4[yo];
    int4 ix = g_it4[xo]; float4 wx = g_wt4[xo];
    const int iyv[4] = {iy.x, iy.y, iy.z, iy.w};
    const float wyv[4] = {wy.x, wy.y, wy.z, wy.w};
    const int ixv[4] = {ix.x, ix.y, ix.z, ix.w};
    const float wxv[4] = {wx.x, wx.y, wx.z, wx.w};
    float s = 0.f;
    #pragma unroll
    for (int a = 0; a < 4; a++) {
        const float* r = su[iyv[a] - ty_lo];
        float h = wxv[0]*r[ixv[0]] + wxv[1]*r[ixv[1]]
                + wxv[2]*r[ixv[2]] + wxv[3]*r[ixv[3]];
        s += wyv[a] * h;
    }
    float iz = g_flag[j] ? 1.f / ((float)NA + 1e-3f * s) : 0.f;
    g_invZ[j] = iz;
    red[t] = iz;
    __syncthreads();
    for (int st2 = 128; st2; st2 >>= 1) {
        if (t < st2) red[t] += red[t + st2];
        __syncthreads();
    }
    if (t == 0) g_s0p[b] = red[0];
}

// ---------------- fused adjoint resize: v = W^T invZ W (block per yi) --------
__global__ void k_vv() {
    __shared__ float svt[96];
    int yi = blockIdx.x, t = threadIdx.x;     // 96 threads
    float a = 0.f;
    for (int yo = 0; yo < 96; yo++)
        a += g_W[yo * 64 + yi] * g_invZ[yo * 96 + t];
    svt[t] = a;
    __syncthreads();
    if (t < 64) {
        float bsum = 0.f;
        for (int xo = 0; xo < 96; xo++)
            bsum += g_W[xo * 64 + t] * svt[xo];
        g_v[yi * 64 + t] = bsum;
    }
}

// ---------------- w_d = 1e-3 * <ref[d], v>, v staged in smem -----------------
__global__ __launch_bounds__(256) void k_w(const float* __restrict__ ref) {
    __shared__ float red[256];
    __shared__ float4 sv[1024];
    int d = blockIdx.x, t = threadIdx.x;
    #pragma unroll
    for (int q = t; q < 1024; q += 256) sv[q] = ((const float4*)g_v)[q];
    __syncthreads();
    const float4* row = (const float4*)(ref + (size_t)d * NPIX);
    float acc = 0.f;
    #pragma unroll
    for (int q = t; q < 1024; q += 256) {
        float4 a = row[q], b = sv[q];
        acc += a.x*b.x + a.y*b.y + a.z*b.z + a.w*b.w;
    }
    red[t] = acc;
    __syncthreads();
    for (int s = 128; s; s >>= 1) {
        if (t < s) red[t] += red[t + s];
        __syncthreads();
    }
    if (t == 0) g_w[d] = red[0] * 1e-3f;
}

// ---------------- y partials: 512 blocks (128 thr) ---------------------------
__global__ __launch_bounds__(128) void k_ypart(const float* __restrict__ ft) {
    __shared__ float sw[DSZ];
    int t = threadIdx.x;
    int p  = blockIdx.x * 128 + t;
    int c0 = blockIdx.y * DSZ;
    if (t < DSZ) sw[t] = g_w[c0 + t];
    __syncthreads();
    float acc = 0.f;
    #pragma unroll
    for (int dd = 0; dd < DSZ; dd++)
        acc += ft[(size_t)(c0 + dd) * NPIX + p] * sw[dd];
    g_yp[p * DCHK + blockIdx.y] = acc;
}

// ---------------- fused yfin + mask (0..35) + x1 (36..44) --------------------
__global__ void k_maskx1(float* __restrict__ maskout) {
    float S0 = 0.f;
    #pragma unroll
    for (int s = 0; s < 36; s++) S0 += g_s0p[s];

    if (blockIdx.x < 36) {
        __shared__ float sy[8][64];
        int b = blockIdx.x, t = threadIdx.x;
        int j0 = b * 256;
        int ty_lo = tap_lo(j0 / 96);
        int nr = min(8, 64 - ty_lo);
        for (int idx = t; idx < nr * 64; idx += 256) {
            int p = (ty_lo + (idx >> 6)) * 64 + (idx & 63);
            sy[idx >> 6][idx & 63] = sum16(g_yp, p);
        }
        __syncthreads();
        int j = j0 + t;
        int yo = j / 96, xo = j % 96;
        int4 iy = g_it4[yo]; float4 wy = g_wt4[yo];
        int4 ix = g_it4[xo]; float4 wx = g_wt4[xo];
        const int iyv[4] = {iy.x, iy.y, iy.z, iy.w};
        const float wyv[4] = {wy.x, wy.y, wy.z, wy.w};
        const int ixv[4] = {ix.x, ix.y, ix.z, ix.w};
        const float wxv[4] = {wx.x, wx.y, wx.z, wx.w};
        float s = 0.f;
        #pragma unroll
        for (int a = 0; a < 4; a++) {
            const float* r = sy[iyv[a] - ty_lo];
            float h = wxv[0]*r[ixv[0]] + wxv[1]*r[ixv[1]]
                    + wxv[2]*r[ixv[2]] + wxv[3]*r[ixv[3]];
            s += wyv[a] * h;
        }
        maskout[j] = S0 + s;
    } else {
        __shared__ float sy[NPIX];            // full y field, 16 KB
        int t = threadIdx.x;
        for (int idx = t; idx < NPIX; idx += 256)
            sy[idx] = sum16(g_yp, idx);
        __syncthreads();
        int k = (blockIdx.x - 36) * 256 + t;
        int yo48 = k / 48, xo48 = k % 48;
        const float step = 95.f / 47.f;
        float ys = yo48 * step, xs = xo48 * step;
        int y0 = (int)floorf(ys), x0 = (int)floorf(xs);
        int y1 = min(y0 + 1, 95), x1i = min(x0 + 1, 95);
        float wyf = ys - (float)y0, wxf = xs - (float)x0;

        auto y96v = [&](int yo, int xo) -> float {
            int4 iy = g_it4[yo]; float4 wy = g_wt4[yo];
            int4 ix = g_it4[xo]; float4 wx = g_wt4[xo];
            const int iyv[4] = {iy.x, iy.y, iy.z, iy.w};
            const float wyv[4] = {wy.x, wy.y, wy.z, wy.w};
            const int ixv[4] = {ix.x, ix.y, ix.z, ix.w};
            const float wxv[4] = {wx.x, wx.y, wx.z, wx.w};
            float s = 0.f;
            #pragma unroll
            for (int a = 0; a < 4; a++) {
                const float* r = sy + iyv[a] * 64;
                float h = wxv[0]*r[ixv[0]] + wxv[1]*r[ixv[1]]
                        + wxv[2]*r[ixv[2]] + wxv[3]*r[ixv[3]];
                s += wyv[a] * h;
            }
            return s;
        };
        float a = y96v(y0, x0),  b = y96v(y0, x1i);
        float c = y96v(y1, x0),  d = y96v(y1, x1i);
        g_x1[k] = S0 + (a * (1.f - wxf) + b * wxf) * (1.f - wyf)
                     + (c * (1.f - wxf) + d * wxf) * wyf;
    }
}

// ---------------- out48[j] = <x1, A[j,:]>, float4 + warp reduce --------------
__global__ __launch_bounds__(256) void k_attn(const float* __restrict__ A) {
    __shared__ float4 sx[576];
    __shared__ float wsum[8];
    int j = blockIdx.x;
    int t = threadIdx.x;
    #pragma unroll
    for (int q = t; q < 576; q += 256) sx[q] = ((const float4*)g_x1)[q];
    __syncthreads();
    const float4* row = (const float4*)(A + (size_t)j * HW48);
    float acc = 0.f;
    #pragma unroll
    for (int q = t; q < 576; q += 256) {
        float4 a = row[q], b = sx[q];
        acc += a.x*b.x + a.y*b.y + a.z*b.z + a.w*b.w;
    }
    acc += __shfl_xor_sync(0xffffffffu, acc, 16);
    acc += __shfl_xor_sync(0xffffffffu, acc, 8);
    acc += __shfl_xor_sync(0xffffffffu, acc, 4);
    acc += __shfl_xor_sync(0xffffffffu, acc, 2);
    acc += __shfl_xor_sync(0xffffffffu, acc, 1);
    if ((t & 31) == 0) wsum[t >> 5] = acc;
    __syncthreads();
    if (t == 0) {
        float s = 0.f;
        #pragma unroll
        for (int wdx = 0; wdx < 8; wdx++) s += wsum[wdx];
        g_out48[j] = s;
    }
}

// ---------------- bilinear (half-pixel, clamp) 48 -> 768 ---------------------
__global__ void k_trimap(float* __restrict__ out) {
    int idx = blockIdx.x * blockDim.x + threadIdx.x;
    if (idx >= 768 * 768) return;
    int ox = idx % 768, oy = idx / 768;
    float sx = (ox + 0.5f) * (1.f / 16.f) - 0.5f;
    float sy = (oy + 0.5f) * (1.f / 16.f) - 0.5f;
    int x0 = (int)floorf(sx), y0 = (int)floorf(sy);
    float wx = sx - (float)x0, wy = sy - (float)y0;
    int x0c = max(x0, 0), x1c = min(x0 + 1, 47);
    int y0c = max(y0, 0), y1c = min(y0 + 1, 47);
    float a = g_out48[y0c * 48 + x0c], b = g_out48[y0c * 48 + x1c];
    float c = g_out48[y1c * 48 + x0c], d = g_out48[y1c * 48 + x1c];
    out[idx] = (a * (1.f - wx) + b * wx) * (1.f - wy) + (c * (1.f - wx) + d * wx) * wy;
}

// ---------------- launch ------------------------------------------------------
extern "C" void kernel_launch(void* const* d_in, const int* in_sizes, int n_in,
                              void* d_out, int out_size) {
    (void)in_sizes; (void)n_in; (void)out_size;
    const float* ref_img = (const float*)d_in[0];
    const float* ft_cor  = (const float*)d_in[1];
    const float* attnA   = (const float*)d_in[2];
    const float* ft_mat  = (const float*)d_in[3];
    const float* guid    = (const float*)d_in[4];

    float* out     = (float*)d_out;
    float* trimap  = out;                       // 768*768
    float* matting = out + 768 * 768;           // 1280*64*64
    float* maskout = matting + 1280 * 64 * 64;  // 9216

    static cudaStream_t s2 = nullptr, s3 = nullptr;
    static cudaEvent_t evA = nullptr, evB = nullptr, ev3 = nullptr;
    if (!s2) {
        cudaStreamCreateWithFlags(&s2, cudaStreamNonBlocking);
        cudaStreamCreateWithFlags(&s3, cudaStreamNonBlocking);
        cudaEventCreateWithFlags(&evA, cudaEventDisableTiming);
        cudaEventCreateWithFlags(&evB, cudaEventDisableTiming);
        cudaEventCreateWithFlags(&ev3, cudaEventDisableTiming);
    }

    // fork: L2-warm ref + attnA, then the big memcpy, on s2; init on s3
    cudaEventRecord(evA, 0);
    cudaStreamWaitEvent(s2, evA, 0);
    cudaStreamWaitEvent(s3, evA, 0);
    k_pref<<<256, 256, 0, s2>>>(ref_img, CDIM * NPIX / 8);
    k_pref<<<256, 256, 0, s2>>>(attnA, HW48 * HW48 / 8);
    cudaMemcpyAsync(matting, ft_mat, (size_t)1280 * 64 * 64 * sizeof(float),
                    cudaMemcpyDeviceToDevice, s2);
    k_init<<<37, 256, 0, s3>>>(guid);
    cudaEventRecord(ev3, s3);

    // main chain
    k_t<<<CDIM, 256>>>(ft_cor);                       // pass 1: ft_cor (cold)
    k_upart<<<dim3(32, DCHK), 128>>>(ref_img);        // pass 2: ref (L2-warm)
    cudaStreamWaitEvent(0, ev3, 0);
    k_invz<<<36, 256>>>();
    k_vv<<<64, 96>>>();
    k_w<<<CDIM, 256>>>(ref_img);                      // pass 3: ref (L2)
    k_ypart<<<dim3(32, DCHK), 128>>>(ft_cor);         // pass 4: ft_cor (L2)
    k_maskx1<<<45, 256>>>(maskout);
    k_attn<<<HW48, 256>>>(attnA);                     // attnA (L2-warm)
    k_trimap<<<(768 * 768 + 255) / 256, 256>>>(trimap);

    // join side stream
    cudaEventRecord(evB, s2);
    cudaStreamWaitEvent(0, evB, 0);
}

// round 17
// speedup vs baseline: 1.0601x; 1.0601x over previous
#include <cuda_runtime.h>
#include <math.h>
#include <stdint.h>

#define NA    9216       // 96*96
#define CDIM  1280
#define NPIX  4096       // 64*64
#define HW48  2304       // 48*48
#define DCHK  16         // d-chunks for column dots
#define DSZ   (CDIM / DCHK)   // 80

// ---------------- scratch (device globals; no allocation allowed) ----------
__device__ float g_t[CDIM];               // t_d
__device__ float g_w[CDIM];               // w_d
__device__ float g_up[NPIX * DCHK];       // u partials, [pixel][chunk]
__device__ float g_yp[NPIX * DCHK];       // y partials, [pixel][chunk]
__device__ float g_v[NPIX];               // adjoint-resized invZ
__device__ float g_invZ[NA];
__device__ float g_s0p[36];               // per-block invZ sums
__device__ unsigned char g_flag[NA];
__device__ float g_x1[HW48];
__device__ float g_out48[HW48];
__device__ int4   g_it4[96];              // cubic taps 64->96
__device__ float4 g_wt4[96];
__device__ float  g_W[96 * 64];           // dense resize matrix W[o][i]
__device__ float  g_cw[64];               // column sums of W

// ---------------- cubic kernel ----------------------------------------------
__device__ __forceinline__ float keys_cubic(float x) {
    x = fabsf(x);
    if (x < 1.f)  return ((1.5f * x - 2.5f) * x) * x + 1.f;
    if (x < 2.f)  return ((-0.5f * x + 2.5f) * x - 4.f) * x + 2.f;
    return 0.f;
}

__device__ __forceinline__ int tap_lo(int yo0) {
    float s = (yo0 + 0.5f) * (64.f / 96.f) - 0.5f;
    return max(0, (int)floorf(s) - 1);
}

// sum the DCHK=16 consecutive partials of pixel p (4 x float4)
__device__ __forceinline__ float sum16(const float* part, int p) {
    const float4* q = (const float4*)(part + p * DCHK);
    float4 a = q[0], b = q[1], c = q[2], d = q[3];
    return ((a.x+a.y)+(a.z+a.w)) + ((b.x+b.y)+(b.z+b.w))
         + ((c.x+c.y)+(c.z+c.w)) + ((d.x+d.y)+(d.z+d.w));
}

// warp-shuffle block reduction (256 threads) -> returns total on thread 0
__device__ __forceinline__ float block_reduce256(float acc, float* wsum, int t) {
    acc += __shfl_xor_sync(0xffffffffu, acc, 16);
    acc += __shfl_xor_sync(0xffffffffu, acc, 8);
    acc += __shfl_xor_sync(0xffffffffu, acc, 4);
    acc += __shfl_xor_sync(0xffffffffu, acc, 2);
    acc += __shfl_xor_sync(0xffffffffu, acc, 1);
    if ((t & 31) == 0) wsum[t >> 5] = acc;
    __syncthreads();
    float s = 0.f;
    if (t == 0) {
        #pragma unroll
        for (int w = 0; w < 8; w++) s += wsum[w];
    }
    return s;
}

// ---------------- init: flag (blocks 0..35) + weights + cw (block 36) -------
__global__ void k_init(const float* __restrict__ guid) {
    if (blockIdx.x < 36) {
        int i = blockIdx.x * 256 + threadIdx.x;
        int by = i / 96, bx = i % 96;
        const float* p = guid + (by * 8) * 768 + bx * 8;
        bool all = true;
        #pragma unroll
        for (int dy = 0; dy < 8; dy++)
            #pragma unroll
            for (int dx = 0; dx < 8; dx++)
                all = all && (p[dy * 768 + dx] > 0.5f);
        g_flag[i] = all ? 1 : 0;
        return;
    }
    int o = threadIdx.x;
    if (o < 96) {
        float s = (o + 0.5f) * (64.f / 96.f) - 0.5f;
        int fl = (int)floorf(s);
        int idx[4]; float w[4]; float tot = 0.f;
        #pragma unroll
        for (int t = 0; t < 4; t++) {
            int ii = fl - 1 + t;
            float ww = (ii >= 0 && ii < 64) ? keys_cubic(s - (float)ii) : 0.f;
            idx[t] = min(max(ii, 0), 63);
            w[t] = ww;
            tot += ww;
        }
        float inv = 1.f / tot;
        g_it4[o] = make_int4(idx[0], idx[1], idx[2], idx[3]);
        g_wt4[o] = make_float4(w[0]*inv, w[1]*inv, w[2]*inv, w[3]*inv);
        float row[64];
        #pragma unroll
        for (int i = 0; i < 64; i++) row[i] = 0.f;
        #pragma unroll
        for (int t = 0; t < 4; t++) row[idx[t]] += w[t] * inv;
        for (int i = 0; i < 64; i++) g_W[o * 64 + i] = row[i];
    }
    __syncthreads();
    if (o < 64) {
        float s = 0.f;
        for (int q = 0; q < 96; q++) s += g_W[q * 64 + o];
        g_cw[o] = s;
    }
}

// ---------------- t_d = <ft_cor[d], Wmap> (cw from g_cw) --------------------
__global__ __launch_bounds__(256) void k_t(const float* __restrict__ ft) {
    __shared__ float scw[64];
    __shared__ float wsum[8];
    int t = threadIdx.x;
    if (t < 64) scw[t] = g_cw[t];
    __syncthreads();
    int d = blockIdx.x;
    const float4* row = (const float4*)(ft + (size_t)d * NPIX);
    float acc = 0.f;
    #pragma unroll
    for (int q = t; q < 1024; q += 256) {
        float4 v = row[q];
        float4 cx = ((const float4*)scw)[q & 15];
        float cy = scw[q >> 4];
        acc += cy * (cx.x*v.x + cx.y*v.y + cx.z*v.z + cx.w*v.w);
    }
    float s = block_reduce256(acc, wsum, t);
    if (t == 0) g_t[d] = s;
}

// ---------------- u partials: 256 blocks, [pixel][chunk] layout --------------
__global__ __launch_bounds__(256) void k_upart(const float* __restrict__ ref) {
    __shared__ float st[DSZ];
    int p  = blockIdx.x * 256 + threadIdx.x;      // 16 x-blocks
    int c0 = blockIdx.y * DSZ;
    if (threadIdx.x < DSZ) st[threadIdx.x] = g_t[c0 + threadIdx.x];
    __syncthreads();
    float acc = 0.f;
    #pragma unroll
    for (int dd = 0; dd < DSZ; dd++)
        acc += ref[(size_t)(c0 + dd) * NPIX + p] * st[dd];
    g_up[p * DCHK + blockIdx.y] = acc;
}

// ---------------- fused: u-window + invZ + s0 partial ------------------------
__global__ void k_invz() {
    __shared__ float su[8][64];
    __shared__ float red[256];
    int b = blockIdx.x, t = threadIdx.x;
    int j0 = b * 256;
    int ty_lo = tap_lo(j0 / 96);
    int nr = min(8, 64 - ty_lo);
    for (int idx = t; idx < nr * 64; idx += 256) {
        int p = (ty_lo + (idx >> 6)) * 64 + (idx & 63);
        su[idx >> 6][idx & 63] = sum16(g_up, p);
    }
    __syncthreads();
    int j = j0 + t;
    int yo = j / 96, xo = j % 96;
    int4 iy = g_it4[yo]; float4 wy = g_wt4[yo];
    int4 ix = g_it4[xo]; float4 wx = g_wt4[xo];
    const int iyv[4] = {iy.x, iy.y, iy.z, iy.w};
    const float wyv[4] = {wy.x, wy.y, wy.z, wy.w};
    const int ixv[4] = {ix.x, ix.y, ix.z, ix.w};
    const float wxv[4] = {wx.x, wx.y, wx.z, wx.w};
    float s = 0.f;
    #pragma unroll
    for (int a = 0; a < 4; a++) {
        const float* r = su[iyv[a] - ty_lo];
        float h = wxv[0]*r[ixv[0]] + wxv[1]*r[ixv[1]]
                + wxv[2]*r[ixv[2]] + wxv[3]*r[ixv[3]];
        s += wyv[a] * h;
    }
    float iz = g_flag[j] ? 1.f / ((float)NA + 1e-3f * s) : 0.f;
    g_invZ[j] = iz;
    red[t] = iz;
    __syncthreads();
    for (int st2 = 128; st2; st2 >>= 1) {
        if (t < st2) red[t] += red[t + st2];
        __syncthreads();
    }
    if (t == 0) g_s0p[b] = red[0];
}

// ---------------- fused adjoint resize: v = W^T invZ W (block per yi) --------
__global__ void k_vv() {
    __shared__ float svt[96];
    int yi = blockIdx.x, t = threadIdx.x;     // 96 threads
    float a = 0.f;
    for (int yo = 0; yo < 96; yo++)
        a += g_W[yo * 64 + yi] * g_invZ[yo * 96 + t];
    svt[t] = a;
    __syncthreads();
    if (t < 64) {
        float bsum = 0.f;
        for (int xo = 0; xo < 96; xo++)
            bsum += g_W[xo * 64 + t] * svt[xo];
        g_v[yi * 64 + t] = bsum;
    }
}

// ---------------- w_d = 1e-3 * <ref[d], v>, v staged in smem -----------------
__global__ __launch_bounds__(256) void k_w(const float* __restrict__ ref) {
    __shared__ float4 sv[1024];
    __shared__ float wsum[8];
    int d = blockIdx.x, t = threadIdx.x;
    #pragma unroll
    for (int q = t; q < 1024; q += 256) sv[q] = ((const float4*)g_v)[q];
    __syncthreads();
    const float4* row = (const float4*)(ref + (size_t)d * NPIX);
    float acc = 0.f;
    #pragma unroll
    for (int q = t; q < 1024; q += 256) {
        float4 a = row[q], b = sv[q];
        acc += a.x*b.x + a.y*b.y + a.z*b.z + a.w*b.w;
    }
    float s = block_reduce256(acc, wsum, t);
    if (t == 0) g_w[d] = s * 1e-3f;
}

// ---------------- y partials --------------------------------------------------
__global__ __launch_bounds__(256) void k_ypart(const float* __restrict__ ft) {
    __shared__ float sw[DSZ];
    int p  = blockIdx.x * 256 + threadIdx.x;
    int c0 = blockIdx.y * DSZ;
    if (threadIdx.x < DSZ) sw[threadIdx.x] = g_w[c0 + threadIdx.x];
    __syncthreads();
    float acc = 0.f;
    #pragma unroll
    for (int dd = 0; dd < DSZ; dd++)
        acc += ft[(size_t)(c0 + dd) * NPIX + p] * sw[dd];
    g_yp[p * DCHK + blockIdx.y] = acc;
}

// ---------------- fused yfin + mask (0..35) + x1 (36..44) --------------------
__global__ void k_maskx1(float* __restrict__ maskout) {
    float S0 = 0.f;
    #pragma unroll
    for (int s = 0; s < 36; s++) S0 += g_s0p[s];

    if (blockIdx.x < 36) {
        __shared__ float sy[8][64];
        int b = blockIdx.x, t = threadIdx.x;
        int j0 = b * 256;
        int ty_lo = tap_lo(j0 / 96);
        int nr = min(8, 64 - ty_lo);
        for (int idx = t; idx < nr * 64; idx += 256) {
            int p = (ty_lo + (idx >> 6)) * 64 + (idx & 63);
            sy[idx >> 6][idx & 63] = sum16(g_yp, p);
        }
        __syncthreads();
        int j = j0 + t;
        int yo = j / 96, xo = j % 96;
        int4 iy = g_it4[yo]; float4 wy = g_wt4[yo];
        int4 ix = g_it4[xo]; float4 wx = g_wt4[xo];
        const int iyv[4] = {iy.x, iy.y, iy.z, iy.w};
        const float wyv[4] = {wy.x, wy.y, wy.z, wy.w};
        const int ixv[4] = {ix.x, ix.y, ix.z, ix.w};
        const float wxv[4] = {wx.x, wx.y, wx.z, wx.w};
        float s = 0.f;
        #pragma unroll
        for (int a = 0; a < 4; a++) {
            const float* r = sy[iyv[a] - ty_lo];
            float h = wxv[0]*r[ixv[0]] + wxv[1]*r[ixv[1]]
                    + wxv[2]*r[ixv[2]] + wxv[3]*r[ixv[3]];
            s += wyv[a] * h;
        }
        maskout[j] = S0 + s;
    } else {
        __shared__ float sy[NPIX];            // full y field, 16 KB
        int t = threadIdx.x;
        for (int idx = t; idx < NPIX; idx += 256)
            sy[idx] = sum16(g_yp, idx);
        __syncthreads();
        int k = (blockIdx.x - 36) * 256 + t;
        int yo48 = k / 48, xo48 = k % 48;
        const float step = 95.f / 47.f;
        float ys = yo48 * step, xs = xo48 * step;
        int y0 = (int)floorf(ys), x0 = (int)floorf(xs);
        int y1 = min(y0 + 1, 95), x1i = min(x0 + 1, 95);
        float wyf = ys - (float)y0, wxf = xs - (float)x0;

        auto y96v = [&](int yo, int xo) -> float {
            int4 iy = g_it4[yo]; float4 wy = g_wt4[yo];
            int4 ix = g_it4[xo]; float4 wx = g_wt4[xo];
            const int iyv[4] = {iy.x, iy.y, iy.z, iy.w};
            const float wyv[4] = {wy.x, wy.y, wy.z, wy.w};
            const int ixv[4] = {ix.x, ix.y, ix.z, ix.w};
            const float wxv[4] = {wx.x, wx.y, wx.z, wx.w};
            float s = 0.f;
            #pragma unroll
            for (int a = 0; a < 4; a++) {
                const float* r = sy + iyv[a] * 64;
                float h = wxv[0]*r[ixv[0]] + wxv[1]*r[ixv[1]]
                        + wxv[2]*r[ixv[2]] + wxv[3]*r[ixv[3]];
                s += wyv[a] * h;
            }
            return s;
        };
        float a = y96v(y0, x0),  b = y96v(y0, x1i);
        float c = y96v(y1, x0),  d = y96v(y1, x1i);
        g_x1[k] = S0 + (a * (1.f - wxf) + b * wxf) * (1.f - wyf)
                     + (c * (1.f - wxf) + d * wxf) * wyf;
    }
}

// ---------------- out48[j] = <x1, A[j,:]>, float4 + warp reduce --------------
__global__ __launch_bounds__(256) void k_attn(const float* __restrict__ A) {
    __shared__ float4 sx[576];
    __shared__ float wsum[8];
    int j = blockIdx.x;
    int t = threadIdx.x;
    #pragma unroll
    for (int q = t; q < 576; q += 256) sx[q] = ((const float4*)g_x1)[q];
    __syncthreads();
    const float4* row = (const float4*)(A + (size_t)j * HW48);
    float acc = 0.f;
    #pragma unroll
    for (int q = t; q < 576; q += 256) {
        float4 a = row[q], b = sx[q];
        acc += a.x*b.x + a.y*b.y + a.z*b.z + a.w*b.w;
    }
    float s = block_reduce256(acc, wsum, t);
    if (t == 0) g_out48[j] = s;
}

// ---------------- bilinear (half-pixel, clamp) 48 -> 768 ---------------------
__global__ void k_trimap(float* __restrict__ out) {
    int idx = blockIdx.x * blockDim.x + threadIdx.x;
    if (idx >= 768 * 768) return;
    int ox = idx % 768, oy = idx / 768;
    float sx = (ox + 0.5f) * (1.f / 16.f) - 0.5f;
    float sy = (oy + 0.5f) * (1.f / 16.f) - 0.5f;
    int x0 = (int)floorf(sx), y0 = (int)floorf(sy);
    float wx = sx - (float)x0, wy = sy - (float)y0;
    int x0c = max(x0, 0), x1c = min(x0 + 1, 47);
    int y0c = max(y0, 0), y1c = min(y0 + 1, 47);
    float a = g_out48[y0c * 48 + x0c], b = g_out48[y0c * 48 + x1c];
    float c = g_out48[y1c * 48 + x0c], d = g_out48[y1c * 48 + x1c];
    out[idx] = (a * (1.f - wx) + b * wx) * (1.f - wy) + (c * (1.f - wx) + d * wx) * wy;
}

// ---------------- launch ------------------------------------------------------
extern "C" void kernel_launch(void* const* d_in, const int* in_sizes, int n_in,
                              void* d_out, int out_size) {
    (void)in_sizes; (void)n_in; (void)out_size;
    const float* ref_img = (const float*)d_in[0];
    const float* ft_cor  = (const float*)d_in[1];
    const float* attnA   = (const float*)d_in[2];
    const float* ft_mat  = (const float*)d_in[3];
    const float* guid    = (const float*)d_in[4];

    float* out     = (float*)d_out;
    float* trimap  = out;                       // 768*768
    float* matting = out + 768 * 768;           // 1280*64*64
    float* maskout = matting + 1280 * 64 * 64;  // 9216

    static cudaStream_t s2 = nullptr;
    static cudaEvent_t evA = nullptr, evB = nullptr;
    if (!s2) {
        cudaStreamCreateWithFlags(&s2, cudaStreamNonBlocking);
        cudaEventCreateWithFlags(&evA, cudaEventDisableTiming);
        cudaEventCreateWithFlags(&evB, cudaEventDisableTiming);
    }

    // fork: big passthrough copy overlaps the whole compute chain
    cudaEventRecord(evA, 0);
    cudaStreamWaitEvent(s2, evA, 0);
    cudaMemcpyAsync(matting, ft_mat, (size_t)1280 * 64 * 64 * sizeof(float),
                    cudaMemcpyDeviceToDevice, s2);

    // main chain (init first: provides flag, taps, W, cw)
    k_init<<<37, 256>>>(guid);
    k_t<<<CDIM, 256>>>(ft_cor);                       // pass 1: ft_cor
    k_upart<<<dim3(16, DCHK), 256>>>(ref_img);        // pass 2: ref
    k_invz<<<36, 256>>>();
    k_vv<<<64, 96>>>();
    k_w<<<CDIM, 256>>>(ref_img);                      // pass 3: ref (L2)
    k_ypart<<<dim3(16, DCHK), 256>>>(ft_cor);         // pass 4: ft_cor (L2)
    k_maskx1<<<45, 256>>>(maskout);
    k_attn<<<HW48, 256>>>(attnA);
    k_trimap<<<(768 * 768 + 255) / 256, 256>>>(trimap);

    // join memcpy
    cudaEventRecord(evB, s2);
    cudaStreamWaitEvent(0, evB, 0);
}